// round 13
// baseline (speedup 1.0000x reference)
#include <cuda_runtime.h>
#include <cuda_fp16.h>
#include <math.h>
#include <cstdint>

#define B_ 2
#define T_ 2048
#define E_ 2048
#define H_ 16
#define D_ 128
#define M_ (B_*T_)             // 4096
#define QKV_N (B_*H_*T_*D_)    // 8388608
#define WN_ (E_*E_)            // 4194304
#define QSCALE 0.08838834764831845f   // 1/sqrt(128)

// ---------------- scratch ----------------------------------------------------
__device__ float  g_Q[QKV_N];          // fp32 Q (pre-rope), head-major [b,h,t,d]
__device__ float  g_K[QKV_N];
__device__ __half g_Qh[QKV_N];         // post-rope, scaled, f16
__device__ __half g_Kh[QKV_N];         // post-rope, f16
__device__ __half g_Vh[QKV_N];
__device__ __half g_Yh[QKV_N];         // attn out [b,t,h*128+d]
__device__ __half g_Xh[M_*E_];
__device__ __half g_Wh[4*WN_];         // Wq,Wk,Wv,Wo f16
__device__ float  g_theta[64];
__device__ float  g_cosT[T_*64];       // RoPE cos table [t][j]
__device__ float  g_sinT[T_*64];       // RoPE sin table [t][j]

// ---------------- helpers ----------------------------------------------------
__device__ __forceinline__ uint32_t smem_u32(const void* p) {
    uint32_t a;
    asm("{ .reg .u64 t; cvta.to.shared.u64 t, %1; cvt.u32.u64 %0, t; }" : "=r"(a) : "l"(p));
    return a;
}
__device__ __forceinline__ void cp16(uint32_t d, const void* g) {
    asm volatile("cp.async.cg.shared.global [%0], [%1], 16;" :: "r"(d), "l"(g));
}
__device__ __forceinline__ void ldsm4(uint32_t (&r)[4], uint32_t addr) {
    asm volatile("ldmatrix.sync.aligned.m8n8.x4.shared.b16 {%0,%1,%2,%3}, [%4];"
        : "=r"(r[0]), "=r"(r[1]), "=r"(r[2]), "=r"(r[3]) : "r"(addr));
}
__device__ __forceinline__ void ldsm4t(uint32_t (&r)[4], uint32_t addr) {
    asm volatile("ldmatrix.sync.aligned.m8n8.x4.trans.shared.b16 {%0,%1,%2,%3}, [%4];"
        : "=r"(r[0]), "=r"(r[1]), "=r"(r[2]), "=r"(r[3]) : "r"(addr));
}
__device__ __forceinline__ void mma16816(float (&d)[4], const uint32_t (&a)[4],
                                         uint32_t b0, uint32_t b1) {
    asm volatile("mma.sync.aligned.m16n8k16.row.col.f32.f16.f16.f32 "
        "{%0,%1,%2,%3},{%4,%5,%6,%7},{%8,%9},{%0,%1,%2,%3};"
        : "+f"(d[0]), "+f"(d[1]), "+f"(d[2]), "+f"(d[3])
        : "r"(a[0]), "r"(a[1]), "r"(a[2]), "r"(a[3]), "r"(b0), "r"(b1));
}
__device__ __forceinline__ uint32_t pack2(float x0, float x1) {
    __half2 h = __floats2half2_rn(x0, x1);
    return *(uint32_t*)&h;
}
__device__ __forceinline__ float qmax(float v) {
    v = fmaxf(v, __shfl_xor_sync(0xffffffffu, v, 1));
    v = fmaxf(v, __shfl_xor_sync(0xffffffffu, v, 2));
    return v;
}
__device__ __forceinline__ float qsum(float v) {
    v += __shfl_xor_sync(0xffffffffu, v, 1);
    v += __shfl_xor_sync(0xffffffffu, v, 2);
    return v;
}

// ---------------------------------------------------------------------------
__global__ void theta_init_kernel() {
    int j = threadIdx.x;
    if (j < 64) g_theta[j] = (float)pow(10000.0, -(double)j / 64.0);
}

// RoPE cos/sin tables: 2048 x 64 angles, computed once.
__global__ void rope_table_kernel() {
    int idx = blockIdx.x * blockDim.x + threadIdx.x;
    if (idx >= T_*64) return;
    int t = idx >> 6, j = idx & 63;
    float ang = (float)(t + 1) * g_theta[j];
    float s, c;
    sincosf(ang, &s, &c);
    g_cosT[idx] = c;
    g_sinT[idx] = s;
}

// x f32 -> f16
__global__ void f2h_kernel(const float* __restrict__ src, __half* __restrict__ dst, int n4) {
    int i = blockIdx.x * blockDim.x + threadIdx.x;
    if (i < n4) {
        float4 v = ((const float4*)src)[i];
        uint32_t* d = (uint32_t*)dst + (size_t)i * 2;
        d[0] = pack2(v.x, v.y);
        d[1] = pack2(v.z, v.w);
    }
}

// all 4 weights f32 -> f16, one launch. grid.y selects matrix.
__global__ void w_f2h_kernel(const float* __restrict__ w0, const float* __restrict__ w1,
                             const float* __restrict__ w2, const float* __restrict__ w3) {
    int i = blockIdx.x * blockDim.x + threadIdx.x;
    if (i >= WN_/4) return;
    const float* srcs[4] = { w0, w1, w2, w3 };
    const float* src = srcs[blockIdx.y];
    float4 v = ((const float4*)src)[i];
    uint32_t* d = (uint32_t*)(g_Wh + (size_t)blockIdx.y * WN_) + (size_t)i * 2;
    d[0] = pack2(v.x, v.y);
    d[1] = pack2(v.z, v.w);
}

// ---------------------------------------------------------------------------
// GEMM core (r9-proven): C tile [128x128] = A[M,K]@W[N,K]^T + bias, f16 HMMA.
// BM=BN=128, BK=64, 256 thr (8 warps 2x4), 3-stage cp.async, 1 barrier/chunk.
// mode 0: ->g_Q fp32 head-major   mode 1: ->g_K fp32 head-major
// mode 2: ->g_Vh f16 head-major   mode 3: ->outF fp32 row-major
// ---------------------------------------------------------------------------
#define MAT_B  (128*144)        // bytes per matrix per stage (128 rows x 144B pitch)
#define STAGE_B (2*MAT_B)       // Ah, Wh
#define GEMM_SMEM (3*STAGE_B)   // 110592

__device__ __forceinline__ void gemm_load_stage(
    uint32_t sb, const __half* Ah, const __half* Bh,
    int m0, int n0, int k0, int tid)
{
    #pragma unroll
    for (int mat = 0; mat < 2; ++mat) {
        const __half* src = mat ? Bh : Ah;
        int rbase = mat ? n0 : m0;
        #pragma unroll
        for (int p = 0; p < 4; ++p) {
            int idx = tid + p * 256;
            int row = idx >> 3, c16 = idx & 7;
            const __half* g = src + (size_t)(rbase + row) * E_ + k0 + c16 * 8;
            cp16(sb + mat * MAT_B + row * 144 + c16 * 16, g);
        }
    }
    asm volatile("cp.async.commit_group;" ::: "memory");
}

__device__ __forceinline__ void gemm_core(
    const __half* __restrict__ Ah, const __half* __restrict__ Bh,
    const float* __restrict__ bias, float* __restrict__ outF,
    int mode, uint32_t sbase)
{
    const int tid = threadIdx.x;
    const int lane = tid & 31;
    const int wid = tid >> 5;
    const int wm = wid >> 2, wn = wid & 3;
    const int n0 = blockIdx.x * 128;
    const int m0 = blockIdx.y * 128;

    float acc[4][4][4] = {};

    gemm_load_stage(sbase,           Ah, Bh, m0, n0, 0,  tid);
    gemm_load_stage(sbase + STAGE_B, Ah, Bh, m0, n0, 64, tid);

    int slot = 0;
    for (int i = 0; i < E_/64; ++i) {
        asm volatile("cp.async.wait_group 1;" ::: "memory");
        __syncthreads();

        if (i + 2 < E_/64) {
            int ps = slot - 1; if (ps < 0) ps += 3;
            gemm_load_stage(sbase + ps * STAGE_B, Ah, Bh, m0, n0, (i + 2) * 64, tid);
        } else {
            asm volatile("cp.async.commit_group;" ::: "memory");
        }

        const uint32_t sb = sbase + slot * STAGE_B;
        #pragma unroll
        for (int k16 = 0; k16 < 4; ++k16) {
            uint32_t ah[4][4];
            #pragma unroll
            for (int mf = 0; mf < 4; ++mf) {
                uint32_t addr = sb + (wm*64 + mf*16 + (lane & 15)) * 144
                              + k16*32 + (lane >> 4) * 16;
                ldsm4(ah[mf], addr);
            }
            uint32_t bh[2][4];
            #pragma unroll
            for (int g = 0; g < 2; ++g) {
                uint32_t addr = sb + MAT_B
                              + (wn*32 + g*16 + (lane & 7) + ((lane >> 4) & 1) * 8) * 144
                              + k16*32 + ((lane >> 3) & 1) * 16;
                ldsm4(bh[g], addr);
            }
            #pragma unroll
            for (int mf = 0; mf < 4; ++mf)
                #pragma unroll
                for (int nf = 0; nf < 4; ++nf) {
                    int g = nf >> 1, h = (nf & 1) * 2;
                    mma16816(acc[mf][nf], ah[mf], bh[g][h], bh[g][h+1]);
                }
        }
        if (++slot == 3) slot = 0;
    }

    // epilogue
    #pragma unroll
    for (int nf = 0; nf < 4; ++nf) {
        int d = wn*32 + nf*8 + (lane & 3) * 2;          // 0..127 within tile
        int gcol = n0 + d;
        float b0 = bias[gcol], b1 = bias[gcol + 1];
        #pragma unroll
        for (int mf = 0; mf < 4; ++mf) {
            int row0 = m0 + wm*64 + mf*16 + (lane >> 2);
            #pragma unroll
            for (int half = 0; half < 2; ++half) {
                int row = row0 + half * 8;
                float v0 = acc[mf][nf][half*2 + 0] + b0;
                float v1 = acc[mf][nf][half*2 + 1] + b1;
                if (mode == 3) {
                    *(float2*)(outF + (size_t)row * E_ + gcol) = make_float2(v0, v1);
                } else {
                    int b = row >> 11, t = row & (T_ - 1), h = blockIdx.x;
                    size_t idx = (((size_t)(b*H_ + h)) * T_ + t) * D_ + d;
                    if (mode == 2) {
                        *(uint32_t*)&g_Vh[idx] = pack2(v0, v1);
                    } else {
                        float* dst = (mode == 0) ? g_Q : g_K;
                        *(float2*)(dst + idx) = make_float2(v0, v1);
                    }
                }
            }
        }
    }
}

// fused Q/K/V projections: grid (16, 32, 3), z selects target
__global__ __launch_bounds__(256) void qkv_gemm(
    const float* __restrict__ bq, const float* __restrict__ bk,
    const float* __restrict__ bv)
{
    extern __shared__ __align__(16) char dsmem[];
    const int mode = blockIdx.z;
    const float* bias = (mode == 0) ? bq : (mode == 1) ? bk : bv;
    gemm_core(g_Xh, g_Wh + (size_t)mode * WN_, bias, nullptr, mode, smem_u32(dsmem));
}

// output projection: grid (16, 32)
__global__ __launch_bounds__(256) void out_gemm(
    const float* __restrict__ bo, float* __restrict__ outF)
{
    extern __shared__ __align__(16) char dsmem[];
    gemm_core(g_Yh, g_Wh + 3*(size_t)WN_, bo, outF, 3, smem_u32(dsmem));
}

// ---------------------------------------------------------------------------
// RoPE + scale (Q only) -> f16, using precomputed cos/sin tables.
// ---------------------------------------------------------------------------
__global__ void rope_kernel() {
    const int total = B_*H_*T_*(D_/2);
    int idx = blockIdx.x * blockDim.x + threadIdx.x;
    if (idx >= total) return;
    int row = idx >> 6;
    int j   = idx & 63;
    int t   = row & (T_ - 1);
    float c = g_cosT[t*64 + j];
    float s = g_sinT[t*64 + j];
    int isK = blockIdx.y;
    const float* src = isK ? g_K : g_Q;
    __half* dst = isK ? g_Kh : g_Qh;
    size_t base = (size_t)row * D_;
    float x0 = src[base + j];
    float x1 = src[base + j + 64];
    float r0 = x0*c - x1*s;
    float r1 = x1*c + x0*s;
    if (!isK) { r0 *= QSCALE; r1 *= QSCALE; }
    dst[base + j]      = __float2half_rn(r0);
    dst[base + j + 64] = __float2half_rn(r1);
}

// ---------------------------------------------------------------------------
// Flash attention, causal, 1-pass f16 HMMA, fp32 softmax.
// grid (8, B*H), 256 threads (8 warps, 16 q-rows each): BQ=128, BKV=64.
// CTA jj processes q-tiles jj and 15-jj (uniform 34 KV-blocks).
// cp.async overlap: V load hidden under S+softmax, next-K load hidden under PV.
// ---------------------------------------------------------------------------
#define AT_ROW 136                       // halves per smem row (128 + 8 pad)
#define AT_ROWB (AT_ROW*2)               // bytes per smem row
#define AT_KTILE (64*AT_ROW)             // halves per 64-row matrix
#define AT_QTILE (128*AT_ROW)            // halves per 128-row matrix
#define ATTN_SMEM ((AT_QTILE + 2*AT_KTILE)*2)   // Q + K + V = 69632 B

__device__ __forceinline__ void attn_cp_tile64(uint32_t dst, const __half* src, int tid) {
    #pragma unroll
    for (int p = 0; p < 4; ++p) {
        int idx = tid + p * 256;
        int row = idx >> 4, c8 = idx & 15;
        cp16(dst + row * AT_ROWB + c8 * 16, src + (size_t)row * D_ + c8 * 8);
    }
}
__device__ __forceinline__ void attn_cp_tile128(uint32_t dst, const __half* src, int tid) {
    #pragma unroll
    for (int p = 0; p < 8; ++p) {
        int idx = tid + p * 256;
        int row = idx >> 4, c8 = idx & 15;
        cp16(dst + row * AT_ROWB + c8 * 16, src + (size_t)row * D_ + c8 * 8);
    }
}

__global__ __launch_bounds__(256) void attn_tc() {
    extern __shared__ __align__(16) __half asmem[];
    __half* sQ = asmem;
    __half* sK = asmem + AT_QTILE;
    __half* sV = asmem + AT_QTILE + AT_KTILE;
    const uint32_t uQ = smem_u32(sQ);
    const uint32_t uK = smem_u32(sK);
    const uint32_t uV = smem_u32(sV);

    const int tid = threadIdx.x;
    const int lane = tid & 31;
    const int w = tid >> 5;              // 0..7, warp handles rows w*16..w*16+15
    const int jj = blockIdx.x;           // 0..7
    const int bh = blockIdx.y;
    const __half* Qhp = g_Qh + (size_t)bh * T_ * D_;
    const __half* Khp = g_Kh + (size_t)bh * T_ * D_;
    const __half* Vhp = g_Vh + (size_t)bh * T_ * D_;

    for (int hh = 0; hh < 2; ++hh) {
        const int qt = hh ? (15 - jj) : jj;
        const int q0 = qt * 128;

        // prologue: Q tile (128 rows) + K_0 tile (one group)
        attn_cp_tile128(uQ, Qhp + (size_t)q0 * D_, tid);
        attn_cp_tile64(uK, Khp, tid);
        asm volatile("cp.async.commit_group;" ::: "memory");

        float of[16][4] = {};
        float m0 = -1e30f, m1 = -1e30f, l0 = 0.f, l1 = 0.f;
        const int nblocks = 2*qt + 2;

        for (int it = 0; it < nblocks; ++it) {
            const int k0 = it * 64;
            const bool near_diag = (it >= nblocks - 2);

            asm volatile("cp.async.wait_group 0;" ::: "memory");   // K_it (and Q) ready
            __syncthreads();                                       // sV free (prev PV done)

            // issue V_it load — hidden under S + softmax
            attn_cp_tile64(uV, Vhp + (size_t)k0 * D_, tid);
            asm volatile("cp.async.commit_group;" ::: "memory");

            // ---- S = Q K^T ----
            float sf[8][4] = {};
            #pragma unroll
            for (int k16 = 0; k16 < 8; ++k16) {
                uint32_t aqh[4];
                uint32_t aaddr = (w*16 + (lane & 15)) * AT_ROWB + k16*32 + (lane >> 4) * 16;
                ldsm4(aqh, uQ + aaddr);
                #pragma unroll
                for (int g = 0; g < 4; ++g) {
                    uint32_t kbh[4];
                    uint32_t baddr = (g*16 + (lane & 7) + ((lane >> 4) & 1) * 8) * AT_ROWB
                                   + k16*32 + ((lane >> 3) & 1) * 16;
                    ldsm4(kbh, uK + baddr);
                    mma16816(sf[2*g],   aqh, kbh[0], kbh[1]);
                    mma16816(sf[2*g+1], aqh, kbh[2], kbh[3]);
                }
            }

            // ---- causal mask (last two blocks only) ----
            const int rg0 = q0 + w*16 + (lane >> 2);
            if (near_diag) {
                #pragma unroll
                for (int n = 0; n < 8; ++n) {
                    int col = k0 + n*8 + (lane & 3) * 2;
                    if (col     > rg0)     sf[n][0] = -1e30f;
                    if (col + 1 > rg0)     sf[n][1] = -1e30f;
                    if (col     > rg0 + 8) sf[n][2] = -1e30f;
                    if (col + 1 > rg0 + 8) sf[n][3] = -1e30f;
                }
            }

            // ---- online softmax ----
            float mx0 = -1e30f, mx1 = -1e30f;
            #pragma unroll
            for (int n = 0; n < 8; ++n) {
                mx0 = fmaxf(mx0, fmaxf(sf[n][0], sf[n][1]));
                mx1 = fmaxf(mx1, fmaxf(sf[n][2], sf[n][3]));
            }
            mx0 = qmax(mx0); mx1 = qmax(mx1);
            float mn0 = fmaxf(m0, mx0), mn1 = fmaxf(m1, mx1);
            float a0 = __expf(m0 - mn0), a1 = __expf(m1 - mn1);
            m0 = mn0; m1 = mn1;

            uint32_t pa[4][4];
            float s0 = 0.f, s1 = 0.f;
            #pragma unroll
            for (int n = 0; n < 8; ++n) {
                float p0 = __expf(sf[n][0] - mn0);
                float p1 = __expf(sf[n][1] - mn0);
                float p2 = __expf(sf[n][2] - mn1);
                float p3 = __expf(sf[n][3] - mn1);
                s0 += p0 + p1; s1 += p2 + p3;
                int kt = n >> 1, o = (n & 1) * 2;
                pa[kt][o + 0] = pack2(p0, p1);
                pa[kt][o + 1] = pack2(p2, p3);
            }
            s0 = qsum(s0); s1 = qsum(s1);
            l0 = l0 * a0 + s0;
            l1 = l1 * a1 + s1;
            #pragma unroll
            for (int n = 0; n < 16; ++n) {
                of[n][0] *= a0; of[n][1] *= a0;
                of[n][2] *= a1; of[n][3] *= a1;
            }

            asm volatile("cp.async.wait_group 0;" ::: "memory");   // V_it ready
            __syncthreads();                                       // sK free (all past S)

            // issue K_{it+1} load — hidden under PV
            if (it + 1 < nblocks) {
                attn_cp_tile64(uK, Khp + (size_t)(k0 + 64) * D_, tid);
                asm volatile("cp.async.commit_group;" ::: "memory");
            }

            // ---- O += P V ----
            #pragma unroll
            for (int kt = 0; kt < 4; ++kt) {
                #pragma unroll
                for (int g = 0; g < 8; ++g) {
                    uint32_t vbh[4];
                    uint32_t vaddr = (kt*16 + (lane & 7) + ((lane >> 3) & 1) * 8) * AT_ROWB
                                   + g*32 + ((lane >> 4) & 1) * 16;
                    ldsm4t(vbh, uV + vaddr);
                    mma16816(of[2*g],   pa[kt], vbh[0], vbh[1]);
                    mma16816(of[2*g+1], pa[kt], vbh[2], vbh[3]);
                }
            }
        }

        // ---- epilogue: normalize, store f16 ----
        float inv0 = 1.0f / l0, inv1 = 1.0f / l1;
        const int b = bh >> 4, h = bh & 15;
        const int row0 = q0 + w*16 + (lane >> 2);
        size_t base0 = ((size_t)(b*T_ + row0)) * E_ + h*D_;
        size_t base1 = base0 + 8 * E_;
        #pragma unroll
        for (int n = 0; n < 16; ++n) {
            int col = n*8 + (lane & 3) * 2;
            *(uint32_t*)&g_Yh[base0 + col] = pack2(of[n][0] * inv0, of[n][1] * inv0);
            *(uint32_t*)&g_Yh[base1 + col] = pack2(of[n][2] * inv1, of[n][3] * inv1);
        }
        __syncthreads();   // all smem reads done before next tile's cp.async writes
    }
}

// ---------------------------------------------------------------------------
extern "C" void kernel_launch(void* const* d_in, const int* in_sizes, int n_in,
                              void* d_out, int out_size) {
    const float* x  = (const float*)d_in[0];
    const float* Wq = (const float*)d_in[1];
    const float* bq = (const float*)d_in[2];
    const float* Wk = (const float*)d_in[3];
    const float* bk = (const float*)d_in[4];
    const float* Wv = (const float*)d_in[5];
    const float* bv = (const float*)d_in[6];
    const float* Wo = (const float*)d_in[7];
    const float* bo = (const float*)d_in[8];
    float* out = (float*)d_out;

    cudaFuncSetAttribute(qkv_gemm, cudaFuncAttributeMaxDynamicSharedMemorySize, GEMM_SMEM);
    cudaFuncSetAttribute(out_gemm, cudaFuncAttributeMaxDynamicSharedMemorySize, GEMM_SMEM);
    cudaFuncSetAttribute(attn_tc,  cudaFuncAttributeMaxDynamicSharedMemorySize, ATTN_SMEM);

    theta_init_kernel<<<1, 64>>>();
    rope_table_kernel<<<(T_*64 + 255)/256, 256>>>();

    __half* Xh;
    cudaGetSymbolAddress((void**)&Xh, g_Xh);

    f2h_kernel<<<(M_*E_/4 + 255)/256, 256>>>(x, Xh, M_*E_/4);
    dim3 gw((WN_/4 + 255)/256, 4);
    w_f2h_kernel<<<gw, 256>>>(Wq, Wk, Wv, Wo);

    dim3 gq(E_/128, M_/128, 3);
    qkv_gemm<<<gq, 256, GEMM_SMEM>>>(bq, bk, bv);

    const int rope_total = B_*H_*T_*(D_/2);
    dim3 g2((rope_total + 255)/256, 2);
    rope_kernel<<<g2, 256>>>();

    dim3 g3(T_/256, B_*H_);          // 8 x 32
    attn_tc<<<g3, 256, ATTN_SMEM>>>();

    dim3 go(E_/128, M_/128);
    out_gemm<<<go, 256, GEMM_SMEM>>>(bo, out);
}

// round 14
// speedup vs baseline: 1.0506x; 1.0506x over previous
#include <cuda_runtime.h>
#include <cuda_fp16.h>
#include <math.h>
#include <cstdint>

#define B_ 2
#define T_ 2048
#define E_ 2048
#define H_ 16
#define D_ 128
#define M_ (B_*T_)             // 4096
#define QKV_N (B_*H_*T_*D_)    // 8388608
#define WN_ (E_*E_)            // 4194304
#define QSCALE 0.08838834764831845f   // 1/sqrt(128)

// ---------------- scratch ----------------------------------------------------
__device__ __half g_Qh[QKV_N];         // post-rope, scaled, f16 [b,h,t,d]
__device__ __half g_Kh[QKV_N];         // post-rope, f16
__device__ __half g_Vh[QKV_N];
__device__ __half g_Yh[QKV_N];         // attn out [b,t,h*128+d]
__device__ __half g_Xh[M_*E_];
__device__ __half g_Wh[4*WN_];         // Wq,Wk,Wv,Wo f16
__device__ float  g_theta[64];
__device__ float  g_cosT[T_*64];       // RoPE cos table [t][j]
__device__ float  g_sinT[T_*64];       // RoPE sin table [t][j]

// ---------------- helpers ----------------------------------------------------
__device__ __forceinline__ uint32_t smem_u32(const void* p) {
    uint32_t a;
    asm("{ .reg .u64 t; cvta.to.shared.u64 t, %1; cvt.u32.u64 %0, t; }" : "=r"(a) : "l"(p));
    return a;
}
__device__ __forceinline__ void cp16(uint32_t d, const void* g) {
    asm volatile("cp.async.cg.shared.global [%0], [%1], 16;" :: "r"(d), "l"(g));
}
__device__ __forceinline__ void ldsm4(uint32_t (&r)[4], uint32_t addr) {
    asm volatile("ldmatrix.sync.aligned.m8n8.x4.shared.b16 {%0,%1,%2,%3}, [%4];"
        : "=r"(r[0]), "=r"(r[1]), "=r"(r[2]), "=r"(r[3]) : "r"(addr));
}
__device__ __forceinline__ void ldsm4t(uint32_t (&r)[4], uint32_t addr) {
    asm volatile("ldmatrix.sync.aligned.m8n8.x4.trans.shared.b16 {%0,%1,%2,%3}, [%4];"
        : "=r"(r[0]), "=r"(r[1]), "=r"(r[2]), "=r"(r[3]) : "r"(addr));
}
__device__ __forceinline__ void mma16816(float (&d)[4], const uint32_t (&a)[4],
                                         uint32_t b0, uint32_t b1) {
    asm volatile("mma.sync.aligned.m16n8k16.row.col.f32.f16.f16.f32 "
        "{%0,%1,%2,%3},{%4,%5,%6,%7},{%8,%9},{%0,%1,%2,%3};"
        : "+f"(d[0]), "+f"(d[1]), "+f"(d[2]), "+f"(d[3])
        : "r"(a[0]), "r"(a[1]), "r"(a[2]), "r"(a[3]), "r"(b0), "r"(b1));
}
__device__ __forceinline__ uint32_t pack2(float x0, float x1) {
    __half2 h = __floats2half2_rn(x0, x1);
    return *(uint32_t*)&h;
}
__device__ __forceinline__ float qmax(float v) {
    v = fmaxf(v, __shfl_xor_sync(0xffffffffu, v, 1));
    v = fmaxf(v, __shfl_xor_sync(0xffffffffu, v, 2));
    return v;
}
__device__ __forceinline__ float qsum(float v) {
    v += __shfl_xor_sync(0xffffffffu, v, 1);
    v += __shfl_xor_sync(0xffffffffu, v, 2);
    return v;
}

// ---------------------------------------------------------------------------
__global__ void theta_init_kernel() {
    int j = threadIdx.x;
    if (j < 64) g_theta[j] = (float)pow(10000.0, -(double)j / 64.0);
}

// RoPE cos/sin tables: 2048 x 64 angles, computed once.
__global__ void rope_table_kernel() {
    int idx = blockIdx.x * blockDim.x + threadIdx.x;
    if (idx >= T_*64) return;
    int t = idx >> 6, j = idx & 63;
    float ang = (float)(t + 1) * g_theta[j];
    float s, c;
    sincosf(ang, &s, &c);
    g_cosT[idx] = c;
    g_sinT[idx] = s;
}

// x f32 -> f16, 8 elems/thread (32B read, 16B write)
__global__ void f2h_kernel(const float* __restrict__ src, __half* __restrict__ dst, int n8) {
    int i = blockIdx.x * blockDim.x + threadIdx.x;
    if (i >= n8) return;
    const float4* s = (const float4*)src + (size_t)i * 2;
    float4 a = s[0], b = s[1];
    uint32_t* d = (uint32_t*)dst + (size_t)i * 4;
    d[0] = pack2(a.x, a.y); d[1] = pack2(a.z, a.w);
    d[2] = pack2(b.x, b.y); d[3] = pack2(b.z, b.w);
}

// all 4 weights f32 -> f16, one launch, 8 elems/thread. grid.y selects matrix.
__global__ void w_f2h_kernel(const float* __restrict__ w0, const float* __restrict__ w1,
                             const float* __restrict__ w2, const float* __restrict__ w3) {
    int i = blockIdx.x * blockDim.x + threadIdx.x;
    if (i >= WN_/8) return;
    const float* srcs[4] = { w0, w1, w2, w3 };
    const float4* s = (const float4*)srcs[blockIdx.y] + (size_t)i * 2;
    float4 a = s[0], b = s[1];
    uint32_t* d = (uint32_t*)(g_Wh + (size_t)blockIdx.y * WN_) + (size_t)i * 4;
    d[0] = pack2(a.x, a.y); d[1] = pack2(a.z, a.w);
    d[2] = pack2(b.x, b.y); d[3] = pack2(b.z, b.w);
}

// ---------------------------------------------------------------------------
// GEMM core (r9-proven): C tile [128x128] = A[M,K]@W[N,K]^T + bias, f16 HMMA.
// BM=BN=128, BK=64, 256 thr (8 warps 2x4), 3-stage cp.async, 1 barrier/chunk.
// mode 0: rope+scale -> g_Qh f16 head-major (fused via smem staging)
// mode 1: rope       -> g_Kh f16 head-major (fused via smem staging)
// mode 2: ->g_Vh f16 head-major   mode 3: ->outF fp32 row-major
// ---------------------------------------------------------------------------
#define MAT_B  (128*144)        // bytes per matrix per stage (128 rows x 144B pitch)
#define STAGE_B (2*MAT_B)       // Ah, Wh
#define GEMM_SMEM (3*STAGE_B)   // 110592
#define STG_PITCH 132           // f32 staging pitch (128 + 4)

__device__ __forceinline__ void gemm_load_stage(
    uint32_t sb, const __half* Ah, const __half* Bh,
    int m0, int n0, int k0, int tid)
{
    #pragma unroll
    for (int mat = 0; mat < 2; ++mat) {
        const __half* src = mat ? Bh : Ah;
        int rbase = mat ? n0 : m0;
        #pragma unroll
        for (int p = 0; p < 4; ++p) {
            int idx = tid + p * 256;
            int row = idx >> 3, c16 = idx & 7;
            const __half* g = src + (size_t)(rbase + row) * E_ + k0 + c16 * 8;
            cp16(sb + mat * MAT_B + row * 144 + c16 * 16, g);
        }
    }
    asm volatile("cp.async.commit_group;" ::: "memory");
}

__device__ __forceinline__ void gemm_core(
    const __half* __restrict__ Ah, const __half* __restrict__ Bh,
    const float* __restrict__ bias, float* __restrict__ outF,
    int mode, char* smem_raw)
{
    const uint32_t sbase = smem_u32(smem_raw);
    const int tid = threadIdx.x;
    const int lane = tid & 31;
    const int wid = tid >> 5;
    const int wm = wid >> 2, wn = wid & 3;
    const int n0 = blockIdx.x * 128;
    const int m0 = blockIdx.y * 128;

    float acc[4][4][4] = {};

    gemm_load_stage(sbase,           Ah, Bh, m0, n0, 0,  tid);
    gemm_load_stage(sbase + STAGE_B, Ah, Bh, m0, n0, 64, tid);

    int slot = 0;
    for (int i = 0; i < E_/64; ++i) {
        asm volatile("cp.async.wait_group 1;" ::: "memory");
        __syncthreads();

        if (i + 2 < E_/64) {
            int ps = slot - 1; if (ps < 0) ps += 3;
            gemm_load_stage(sbase + ps * STAGE_B, Ah, Bh, m0, n0, (i + 2) * 64, tid);
        } else {
            asm volatile("cp.async.commit_group;" ::: "memory");
        }

        const uint32_t sb = sbase + slot * STAGE_B;
        #pragma unroll
        for (int k16 = 0; k16 < 4; ++k16) {
            uint32_t ah[4][4];
            #pragma unroll
            for (int mf = 0; mf < 4; ++mf) {
                uint32_t addr = sb + (wm*64 + mf*16 + (lane & 15)) * 144
                              + k16*32 + (lane >> 4) * 16;
                ldsm4(ah[mf], addr);
            }
            uint32_t bh[2][4];
            #pragma unroll
            for (int g = 0; g < 2; ++g) {
                uint32_t addr = sb + MAT_B
                              + (wn*32 + g*16 + (lane & 7) + ((lane >> 4) & 1) * 8) * 144
                              + k16*32 + ((lane >> 3) & 1) * 16;
                ldsm4(bh[g], addr);
            }
            #pragma unroll
            for (int mf = 0; mf < 4; ++mf)
                #pragma unroll
                for (int nf = 0; nf < 4; ++nf) {
                    int g = nf >> 1, h = (nf & 1) * 2;
                    mma16816(acc[mf][nf], ah[mf], bh[g][h], bh[g][h+1]);
                }
        }
        if (++slot == 3) slot = 0;
    }

    if (mode <= 1) {
        // ---- fused RoPE epilogue: stage fp32 tile in smem, rope, write f16 ----
        __syncthreads();   // all warps done reading pipeline smem
        float* stg = (float*)smem_raw;
        #pragma unroll
        for (int nf = 0; nf < 4; ++nf) {
            int d = wn*32 + nf*8 + (lane & 3) * 2;
            float b0 = bias[n0 + d], b1 = bias[n0 + d + 1];
            #pragma unroll
            for (int mf = 0; mf < 4; ++mf) {
                int rl0 = wm*64 + mf*16 + (lane >> 2);
                #pragma unroll
                for (int half = 0; half < 2; ++half) {
                    int rl = rl0 + half * 8;
                    stg[rl*STG_PITCH + d]     = acc[mf][nf][half*2 + 0] + b0;
                    stg[rl*STG_PITCH + d + 1] = acc[mf][nf][half*2 + 1] + b1;
                }
            }
        }
        __syncthreads();
        const int h = blockIdx.x;
        __half* dst = (mode == 0) ? g_Qh : g_Kh;
        for (int i = tid; i < 128*32; i += 256) {
            int rl = i >> 5;             // local row 0..127
            int p  = i & 31;             // pair group, j = 2p
            int row = m0 + rl;
            int b = row >> 11, t = row & (T_ - 1);
            float x0 = stg[rl*STG_PITCH + 2*p];
            float x1 = stg[rl*STG_PITCH + 2*p + 1];
            float y0 = stg[rl*STG_PITCH + 2*p + 64];
            float y1 = stg[rl*STG_PITCH + 2*p + 65];
            float c0 = g_cosT[t*64 + 2*p],     s0 = g_sinT[t*64 + 2*p];
            float c1 = g_cosT[t*64 + 2*p + 1], s1 = g_sinT[t*64 + 2*p + 1];
            float r0 = x0*c0 - y0*s0;
            float r1 = x1*c1 - y1*s1;
            float r2 = y0*c0 + x0*s0;
            float r3 = y1*c1 + x1*s1;
            if (mode == 0) { r0 *= QSCALE; r1 *= QSCALE; r2 *= QSCALE; r3 *= QSCALE; }
            size_t base = (((size_t)(b*H_ + h)) * T_ + t) * D_;
            *(uint32_t*)&dst[base + 2*p]      = pack2(r0, r1);
            *(uint32_t*)&dst[base + 2*p + 64] = pack2(r2, r3);
        }
        return;
    }

    // ---- plain epilogue (modes 2, 3) ----
    #pragma unroll
    for (int nf = 0; nf < 4; ++nf) {
        int d = wn*32 + nf*8 + (lane & 3) * 2;
        int gcol = n0 + d;
        float b0 = bias[gcol], b1 = bias[gcol + 1];
        #pragma unroll
        for (int mf = 0; mf < 4; ++mf) {
            int row0 = m0 + wm*64 + mf*16 + (lane >> 2);
            #pragma unroll
            for (int half = 0; half < 2; ++half) {
                int row = row0 + half * 8;
                float v0 = acc[mf][nf][half*2 + 0] + b0;
                float v1 = acc[mf][nf][half*2 + 1] + b1;
                if (mode == 3) {
                    *(float2*)(outF + (size_t)row * E_ + gcol) = make_float2(v0, v1);
                } else {
                    int b = row >> 11, t = row & (T_ - 1), h = blockIdx.x;
                    size_t idx = (((size_t)(b*H_ + h)) * T_ + t) * D_ + d;
                    *(uint32_t*)&g_Vh[idx] = pack2(v0, v1);
                }
            }
        }
    }
}

// fused Q/K/V projections: grid (16, 32, 3), z selects target
__global__ __launch_bounds__(256) void qkv_gemm(
    const float* __restrict__ bq, const float* __restrict__ bk,
    const float* __restrict__ bv)
{
    extern __shared__ __align__(16) char dsmem[];
    const int mode = blockIdx.z;
    const float* bias = (mode == 0) ? bq : (mode == 1) ? bk : bv;
    gemm_core(g_Xh, g_Wh + (size_t)mode * WN_, bias, nullptr, mode, dsmem);
}

// output projection: grid (16, 32)
__global__ __launch_bounds__(256) void out_gemm(
    const float* __restrict__ bo, float* __restrict__ outF)
{
    extern __shared__ __align__(16) char dsmem[];
    gemm_core(g_Yh, g_Wh + 3*(size_t)WN_, bo, outF, 3, dsmem);
}

// ---------------------------------------------------------------------------
// Flash attention (r9-proven), causal, 1-pass f16 HMMA, fp32 softmax.
// grid (T/64, B*H), 128 threads (4 warps). BQ=64 (16 rows/warp), BKV=64.
// cp.async overlap: V load hidden under S+softmax, next-K load hidden under PV.
// Heavy q-tiles mapped to low blockIdx (wave-1 start).
// ---------------------------------------------------------------------------
#define AT_ROW 136                       // halves per smem row (128 + 8 pad)
#define AT_ROWB (AT_ROW*2)               // bytes per smem row
#define AT_TILE (64*AT_ROW)              // halves per matrix
#define ATTN_SMEM (3*AT_TILE*2)          // Q, K, V = 52224 B

__device__ __forceinline__ void attn_cp_tile(uint32_t dst, const __half* src, int tid) {
    #pragma unroll
    for (int p = 0; p < 8; ++p) {
        int idx = tid + p * 128;
        int row = idx >> 4, c8 = idx & 15;
        cp16(dst + row * AT_ROWB + c8 * 16, src + (size_t)row * D_ + c8 * 8);
    }
}

__global__ __launch_bounds__(128) void attn_tc() {
    extern __shared__ __align__(16) __half asmem[];
    __half* sQ = asmem;
    __half* sK = asmem + AT_TILE;
    __half* sV = asmem + 2*AT_TILE;
    const uint32_t uQ = smem_u32(sQ);
    const uint32_t uK = smem_u32(sK);
    const uint32_t uV = smem_u32(sV);

    const int tid = threadIdx.x;
    const int lane = tid & 31;
    const int w = tid >> 5;
    const int q0 = (int)(gridDim.x - 1 - blockIdx.x) * 64;   // heavy tiles first
    const int bh = blockIdx.y;
    const __half* Qhp = g_Qh + (size_t)bh * T_ * D_;
    const __half* Khp = g_Kh + (size_t)bh * T_ * D_;
    const __half* Vhp = g_Vh + (size_t)bh * T_ * D_;

    // prologue: Q tile + K_0 tile (one group)
    attn_cp_tile(uQ, Qhp + (size_t)q0 * D_, tid);
    attn_cp_tile(uK, Khp, tid);
    asm volatile("cp.async.commit_group;" ::: "memory");

    float of[16][4] = {};
    float m0 = -1e30f, m1 = -1e30f, l0 = 0.f, l1 = 0.f;
    const int nblocks = q0/64 + 1;

    for (int it = 0; it < nblocks; ++it) {
        const int k0 = it * 64;
        const bool diag = (it == nblocks - 1);

        asm volatile("cp.async.wait_group 0;" ::: "memory");   // K_it (and Q) ready
        __syncthreads();                                       // sV free (prev PV done)

        // issue V_it load — hidden under S + softmax
        attn_cp_tile(uV, Vhp + (size_t)k0 * D_, tid);
        asm volatile("cp.async.commit_group;" ::: "memory");

        // ---- S = Q K^T ----
        float sf[8][4] = {};
        #pragma unroll
        for (int k16 = 0; k16 < 8; ++k16) {
            uint32_t aqh[4];
            uint32_t aaddr = (w*16 + (lane & 15)) * AT_ROWB + k16*32 + (lane >> 4) * 16;
            ldsm4(aqh, uQ + aaddr);
            #pragma unroll
            for (int g = 0; g < 4; ++g) {
                uint32_t kbh[4];
                uint32_t baddr = (g*16 + (lane & 7) + ((lane >> 4) & 1) * 8) * AT_ROWB
                               + k16*32 + ((lane >> 3) & 1) * 16;
                ldsm4(kbh, uK + baddr);
                mma16816(sf[2*g],   aqh, kbh[0], kbh[1]);
                mma16816(sf[2*g+1], aqh, kbh[2], kbh[3]);
            }
        }

        // ---- mask (diagonal block only) ----
        const int rg0 = q0 + w*16 + (lane >> 2);
        if (diag) {
            #pragma unroll
            for (int n = 0; n < 8; ++n) {
                int col = k0 + n*8 + (lane & 3) * 2;
                if (col     > rg0)     sf[n][0] = -1e30f;
                if (col + 1 > rg0)     sf[n][1] = -1e30f;
                if (col     > rg0 + 8) sf[n][2] = -1e30f;
                if (col + 1 > rg0 + 8) sf[n][3] = -1e30f;
            }
        }

        // ---- online softmax ----
        float mx0 = -1e30f, mx1 = -1e30f;
        #pragma unroll
        for (int n = 0; n < 8; ++n) {
            mx0 = fmaxf(mx0, fmaxf(sf[n][0], sf[n][1]));
            mx1 = fmaxf(mx1, fmaxf(sf[n][2], sf[n][3]));
        }
        mx0 = qmax(mx0); mx1 = qmax(mx1);
        float mn0 = fmaxf(m0, mx0), mn1 = fmaxf(m1, mx1);
        float a0 = __expf(m0 - mn0), a1 = __expf(m1 - mn1);
        m0 = mn0; m1 = mn1;

        uint32_t pa[4][4];
        float s0 = 0.f, s1 = 0.f;
        #pragma unroll
        for (int n = 0; n < 8; ++n) {
            float p0 = __expf(sf[n][0] - mn0);
            float p1 = __expf(sf[n][1] - mn0);
            float p2 = __expf(sf[n][2] - mn1);
            float p3 = __expf(sf[n][3] - mn1);
            s0 += p0 + p1; s1 += p2 + p3;
            int kt = n >> 1, o = (n & 1) * 2;
            pa[kt][o + 0] = pack2(p0, p1);
            pa[kt][o + 1] = pack2(p2, p3);
        }
        s0 = qsum(s0); s1 = qsum(s1);
        l0 = l0 * a0 + s0;
        l1 = l1 * a1 + s1;
        #pragma unroll
        for (int n = 0; n < 16; ++n) {
            of[n][0] *= a0; of[n][1] *= a0;
            of[n][2] *= a1; of[n][3] *= a1;
        }

        asm volatile("cp.async.wait_group 0;" ::: "memory");   // V_it ready
        __syncthreads();                                       // sK free (all past S)

        // issue K_{it+1} load — hidden under PV
        if (it + 1 < nblocks) {
            attn_cp_tile(uK, Khp + (size_t)(k0 + 64) * D_, tid);
            asm volatile("cp.async.commit_group;" ::: "memory");
        }

        // ---- O += P V ----
        #pragma unroll
        for (int kt = 0; kt < 4; ++kt) {
            #pragma unroll
            for (int g = 0; g < 8; ++g) {
                uint32_t vbh[4];
                uint32_t vaddr = (kt*16 + (lane & 7) + ((lane >> 3) & 1) * 8) * AT_ROWB
                               + g*32 + ((lane >> 4) & 1) * 16;
                ldsm4t(vbh, uV + vaddr);
                mma16816(of[2*g],   pa[kt], vbh[0], vbh[1]);
                mma16816(of[2*g+1], pa[kt], vbh[2], vbh[3]);
            }
        }
    }

    // ---- epilogue: normalize, store f16 ----
    float inv0 = 1.0f / l0, inv1 = 1.0f / l1;
    const int b = bh >> 4, h = bh & 15;
    const int row0 = q0 + w*16 + (lane >> 2);
    size_t base0 = ((size_t)(b*T_ + row0)) * E_ + h*D_;
    size_t base1 = base0 + 8 * E_;
    #pragma unroll
    for (int n = 0; n < 16; ++n) {
        int col = n*8 + (lane & 3) * 2;
        *(uint32_t*)&g_Yh[base0 + col] = pack2(of[n][0] * inv0, of[n][1] * inv0);
        *(uint32_t*)&g_Yh[base1 + col] = pack2(of[n][2] * inv1, of[n][3] * inv1);
    }
}

// ---------------------------------------------------------------------------
extern "C" void kernel_launch(void* const* d_in, const int* in_sizes, int n_in,
                              void* d_out, int out_size) {
    const float* x  = (const float*)d_in[0];
    const float* Wq = (const float*)d_in[1];
    const float* bq = (const float*)d_in[2];
    const float* Wk = (const float*)d_in[3];
    const float* bk = (const float*)d_in[4];
    const float* Wv = (const float*)d_in[5];
    const float* bv = (const float*)d_in[6];
    const float* Wo = (const float*)d_in[7];
    const float* bo = (const float*)d_in[8];
    float* out = (float*)d_out;

    cudaFuncSetAttribute(qkv_gemm, cudaFuncAttributeMaxDynamicSharedMemorySize, GEMM_SMEM);
    cudaFuncSetAttribute(out_gemm, cudaFuncAttributeMaxDynamicSharedMemorySize, GEMM_SMEM);
    cudaFuncSetAttribute(attn_tc,  cudaFuncAttributeMaxDynamicSharedMemorySize, ATTN_SMEM);

    theta_init_kernel<<<1, 64>>>();
    rope_table_kernel<<<(T_*64 + 255)/256, 256>>>();

    __half* Xh;
    cudaGetSymbolAddress((void**)&Xh, g_Xh);

    f2h_kernel<<<(M_*E_/8 + 255)/256, 256>>>(x, Xh, M_*E_/8);
    dim3 gw((WN_/8 + 255)/256, 4);
    w_f2h_kernel<<<gw, 256>>>(Wq, Wk, Wv, Wo);

    dim3 gq(E_/128, M_/128, 3);
    qkv_gemm<<<gq, 256, GEMM_SMEM>>>(bq, bk, bv);

    dim3 g3(T_/64, B_*H_);
    attn_tc<<<g3, 128, ATTN_SMEM>>>();

    dim3 go(E_/128, M_/128);
    out_gemm<<<go, 256, GEMM_SMEM>>>(bo, out);
}